// round 15
// baseline (speedup 1.0000x reference)
#include <cuda_runtime.h>
#include <cuda_fp16.h>

// AdaptiveFilter: per-pixel learned bilateral filter.
// PY=4 vertical blocking, tile 32x16, 128-thread CTAs.
// Logits staged in smem as fp16 (prescaled by log2 e, stride 9 half2/pixel,
// conflict-free). x1/x2 staged as half2 (saves 3.4KB smem). No pad column
// (BX=32: all lanes of a warp read the same smem row => no row conflicts).
// smem ~34.7KB -> 6 CTAs/SM (24 warps).
// out_c(p) = sum_k x_c(p+dk) * e_k / sum_k e_k,
//   e_k = 2^( w_k*log2e - (S*d_k)^2 ),  S = sqrt(50*log2e),
//   d_k = sum_c |g_c(p+dk)-g_c(p)|  (guidance pre-scaled by S in smem).
// Softmax normalizer cancels in the ratio.

namespace {
constexpr int B = 2, C = 3, H = 512, W = 512;
constexpr int BX = 32, BY = 4;       // 128 threads; warp = one 32-col row group
constexpr int NT = BX * BY;
constexpr int PY = 4;                // pixels per thread (vertical)
constexpr int TW = BX;               // 32
constexpr int TH = BY * PY;          // 16
constexpr int HALO = 3;
constexpr int SW = TW + 2 * HALO;    // 38
constexpr int SH = TH + 2 * HALO;    // 22
constexpr int NPIX = TW * TH;        // 512 pixels per tile
constexpr int LS = 9;                // logit stride per pixel in half2 units
constexpr float LOG2E = 1.4426950408889634f;
constexpr float GS = 8.49321796f;    // sqrt(50*log2e)
}

__device__ __forceinline__ float ex2f(float v) {
    float r;
    asm("ex2.approx.f32 %0, %1;" : "=f"(r) : "f"(v));
    return r;
}

__global__ __launch_bounds__(NT, 6)
void adaptive_filter_kernel(const float* __restrict__ x,
                            const float* __restrict__ g,
                            const float* __restrict__ w0,
                            float* __restrict__ out) {
    // Packed shared tiles: sgx = (S*g0, S*g1, S*g2, x0), sxh = half2(x1, x2).
    __shared__ float4 sgx[SH][SW];
    __shared__ __half2 sxh[SH][SW];
    // Staged logits: 16 halves (8 half2) per pixel at stride 9 half2.
    __shared__ __half2 slog[NPIX * LS + 8];

    const int b   = blockIdx.z;
    const int h0  = blockIdx.y * TH;
    const int w0c = blockIdx.x * TW;
    const int tid = threadIdx.y * BX + threadIdx.x;

    const float* __restrict__ gb = g + (size_t)b * C * H * W;
    const float* __restrict__ xb = x + (size_t)b * C * H * W;

    // ---- Stage logits: 512 px * 4 float4 = 2048 float4 (128 per tile row),
    // dense cooperative LDG.128, prescale by log2e, pack fp16, scatter.
    {
        const float4* __restrict__ wsrc = reinterpret_cast<const float4*>(w0);
#pragma unroll
        for (int k = 0; k < 16; ++k) {
            const int c = tid + NT * k;    // chunk 0..2047
            const int r = c >> 7;          // tile pixel row (0..15)
            const int f = c & 127;         // float4 within this row's 128
            const float4 t = __ldg(
                &wsrc[((size_t)b * H * W + (size_t)(h0 + r) * W + w0c) * 4 + f]);
            const int id = r * 32 + (f >> 2);  // tile-local pixel id
            const int q  = f & 3;              // float4 slot within pixel
            slog[id * LS + q * 2]     = __floats2half2_rn(t.x * LOG2E, t.y * LOG2E);
            slog[id * LS + q * 2 + 1] = __floats2half2_rn(t.z * LOG2E, t.w * LOG2E);
        }
    }

    // ---- Halo load with reflect padding (pad=3 << 512, one reflection).
    for (int idx = tid; idx < SH * SW; idx += NT) {
        const int ty = idx / SW;
        const int tx = idx - ty * SW;
        int gy = h0 + ty - HALO;
        gy = gy < 0 ? -gy : (gy >= H ? 2 * H - 2 - gy : gy);
        int gx = w0c + tx - HALO;
        gx = gx < 0 ? -gx : (gx >= W ? 2 * W - 2 - gx : gx);
        const int p = gy * W + gx;
        sgx[ty][tx] = make_float4(gb[p] * GS, gb[H * W + p] * GS,
                                  gb[2 * H * W + p] * GS, xb[p]);
        sxh[ty][tx] = __floats2half2_rn(xb[H * W + p], xb[2 * H * W + p]);
    }
    __syncthreads();

    const int tx  = threadIdx.x;            // 0..31 (column within tile)
    const int py0 = threadIdx.y * PY;       // tile-local row of pixel 0
    const int h   = h0 + py0;
    const int w   = w0c + tx;

    // Center guidance (pre-scaled) per pixel.
    float cx[PY], cy[PY], cz[PY];
#pragma unroll
    for (int p = 0; p < PY; ++p) {
        const float4 c = sgx[py0 + p + HALO][tx + HALO];
        cx[p] = c.x; cy[p] = c.y; cz[p] = c.z;
    }

    float n0[PY], n1[PY], n2[PY], dn[PY];
#pragma unroll
    for (int p = 0; p < PY; ++p) { n0[p] = n1[p] = n2[p] = dn[p] = 0.f; }

#pragma unroll
    for (int i = 0; i < PY + 6; ++i) {       // window rows py0+i
        const int row = py0 + i;

        // Kernel-row logits from fp16 smem. Pixel p valid iff 0<=i-p<=6.
        float wl[PY][4];
#pragma unroll
        for (int p = 0; p < PY; ++p) {
            const int kr = i - p;
            if (kr < 0 || kr > 6) continue;
            const int hi = kr < 4 ? kr : 6 - kr;
            const int base = ((py0 + p) * 32 + tx) * LS + hi * 2;
            const float2 fa = __half22float2(slog[base]);
            const float2 fb = __half22float2(slog[base + 1]);
            wl[p][0] = fa.x; wl[p][1] = fa.y; wl[p][2] = fb.x; wl[p][3] = fb.y;
        }

#pragma unroll
        for (int j = 0; j < 7; ++j) {
            const int hj = j < 4 ? j : 6 - j;
            // One shared read per (i,j) cell, consumed by all valid pixels.
            const float4 v = sgx[row][tx + j];
            const float2 u = __half22float2(sxh[row][tx + j]);
#pragma unroll
            for (int p = 0; p < PY; ++p) {
                if (i - p < 0 || i - p > 6) continue;
                const float s = fabsf(v.x - cx[p]) + fabsf(v.y - cy[p]) +
                                fabsf(v.z - cz[p]);
                const float e = ex2f(fmaf(s, -s, wl[p][hj]));
                n0[p] = fmaf(v.w, e, n0[p]);
                n1[p] = fmaf(u.x, e, n1[p]);
                n2[p] = fmaf(u.y, e, n2[p]);
                dn[p] += e;
            }
        }
    }

    const size_t o0 = ((size_t)b * C * H + (size_t)h) * W + w;
#pragma unroll
    for (int p = 0; p < PY; ++p) {
        const float inv = __fdividef(1.0f, dn[p]);
        const size_t o = o0 + (size_t)p * W;
        out[o]                     = n0[p] * inv;
        out[o + (size_t)H * W]     = n1[p] * inv;
        out[o + (size_t)2 * H * W] = n2[p] * inv;
    }
}

extern "C" void kernel_launch(void* const* d_in, const int* in_sizes, int n_in,
                              void* d_out, int out_size) {
    const float* x  = (const float*)d_in[0];
    const float* g  = (const float*)d_in[1];
    const float* w0 = (const float*)d_in[2];
    float* out = (float*)d_out;

    dim3 block(BX, BY);
    dim3 grid(W / TW, H / TH, B);
    adaptive_filter_kernel<<<grid, block>>>(x, g, w0, out);
}

// round 16
// speedup vs baseline: 1.1637x; 1.1637x over previous
#include <cuda_runtime.h>
#include <cuda_fp16.h>

// AdaptiveFilter: per-pixel learned bilateral filter.
// PY=2 vertical blocking, tile 32x16, 256-thread CTAs (BX=32, BY=8),
// logits staged in shared memory as fp16 (prescaled by log2 e, 9-half2/pixel
// stride -> conflict-free LDS.32). 4 CTAs/SM = 32 warps at natural regs.
// out_c(p) = sum_k x_c(p+dk) * e_k / sum_k e_k,
//   e_k = 2^( w_k*log2e - (S*d_k)^2 ),  S = sqrt(50*log2e),
//   d_k = sum_c |g_c(p+dk)-g_c(p)|  (guidance pre-scaled by S in smem).
// Softmax normalizer cancels in the ratio.

namespace {
constexpr int B = 2, C = 3, H = 512, W = 512;
constexpr int BX = 32, BY = 8;       // 256 threads; warp = one 32-col row
constexpr int NT = BX * BY;
constexpr int PY = 2;                // pixels per thread (vertical)
constexpr int TW = BX;               // 32
constexpr int TH = BY * PY;          // 16
constexpr int HALO = 3;
constexpr int SW = TW + 2 * HALO;    // 38
constexpr int SH = TH + 2 * HALO;    // 22
constexpr int NPIX = TW * TH;        // 512 pixels per tile
constexpr int LS = 9;                // logit stride per pixel in half2 units
constexpr float LOG2E = 1.4426950408889634f;
constexpr float GS = 8.49321796f;    // sqrt(50*log2e)
}

__device__ __forceinline__ float ex2f(float v) {
    float r;
    asm("ex2.approx.f32 %0, %1;" : "=f"(r) : "f"(v));
    return r;
}

__global__ __launch_bounds__(NT, 4)
void adaptive_filter_kernel(const float* __restrict__ x,
                            const float* __restrict__ g,
                            const float* __restrict__ w0,
                            float* __restrict__ out) {
    // Packed shared tiles: sgx = (S*g0, S*g1, S*g2, x0), sx2 = (x1, x2).
    __shared__ float4 sgx[SH][SW + 1];
    __shared__ float2 sx2[SH][SW + 1];
    // Staged logits: 16 halves (8 half2) per pixel at stride 9 half2.
    __shared__ __half2 slog[NPIX * LS + 8];

    const int b   = blockIdx.z;
    const int h0  = blockIdx.y * TH;
    const int w0c = blockIdx.x * TW;
    const int tid = threadIdx.y * BX + threadIdx.x;

    const float* __restrict__ gb = g + (size_t)b * C * H * W;
    const float* __restrict__ xb = x + (size_t)b * C * H * W;

    // ---- Stage logits: 512 px * 4 float4 = 2048 float4 (128 per tile row),
    // dense cooperative LDG.128, prescale by log2e, pack fp16, scatter.
    {
        const float4* __restrict__ wsrc = reinterpret_cast<const float4*>(w0);
#pragma unroll
        for (int k = 0; k < 8; ++k) {
            const int c = tid + NT * k;    // chunk 0..2047
            const int r = c >> 7;          // tile pixel row (0..15)
            const int f = c & 127;         // float4 within this row's 128
            const float4 t = __ldg(
                &wsrc[((size_t)b * H * W + (size_t)(h0 + r) * W + w0c) * 4 + f]);
            const int id = r * 32 + (f >> 2);  // tile-local pixel id
            const int q  = f & 3;              // float4 slot within pixel
            slog[id * LS + q * 2]     = __floats2half2_rn(t.x * LOG2E, t.y * LOG2E);
            slog[id * LS + q * 2 + 1] = __floats2half2_rn(t.z * LOG2E, t.w * LOG2E);
        }
    }

    // ---- Halo load with reflect padding (pad=3 << 512, one reflection).
    for (int idx = tid; idx < SH * SW; idx += NT) {
        const int ty = idx / SW;
        const int tx = idx - ty * SW;
        int gy = h0 + ty - HALO;
        gy = gy < 0 ? -gy : (gy >= H ? 2 * H - 2 - gy : gy);
        int gx = w0c + tx - HALO;
        gx = gx < 0 ? -gx : (gx >= W ? 2 * W - 2 - gx : gx);
        const int p = gy * W + gx;
        sgx[ty][tx] = make_float4(gb[p] * GS, gb[H * W + p] * GS,
                                  gb[2 * H * W + p] * GS, xb[p]);
        sx2[ty][tx] = make_float2(xb[H * W + p], xb[2 * H * W + p]);
    }
    __syncthreads();

    const int tx  = threadIdx.x;            // 0..31 (column within tile)
    const int py0 = threadIdx.y * PY;       // tile-local row of pixel 0
    const int h   = h0 + py0;
    const int w   = w0c + tx;

    // Per-pixel logit bases (half2 index into slog).
    const int lb0 = (py0 * 32 + tx) * LS;
    const int lb1 = ((py0 + 1) * 32 + tx) * LS;

    // Center guidance (pre-scaled) per pixel.
    const float4 cc0 = sgx[py0 + HALO][tx + HALO];
    const float4 cc1 = sgx[py0 + 1 + HALO][tx + HALO];

    float n0[PY] = {0.f, 0.f}, n1[PY] = {0.f, 0.f},
          n2[PY] = {0.f, 0.f}, dn[PY] = {0.f, 0.f};

#pragma unroll
    for (int i = 0; i < 8; ++i) {            // window rows py0+i
        const int row = py0 + i;

        // Kernel-row logits from fp16 smem; compile-time predication.
        float wl0[4], wl1[4];
        if (i <= 6) {                        // pixel 0: kernel row i
            const int hi = i < 4 ? i : 6 - i;
            const float2 fa = __half22float2(slog[lb0 + hi * 2]);
            const float2 fb = __half22float2(slog[lb0 + hi * 2 + 1]);
            wl0[0] = fa.x; wl0[1] = fa.y; wl0[2] = fb.x; wl0[3] = fb.y;
        }
        if (i >= 1) {                        // pixel 1: kernel row i-1
            const int kr = i - 1;
            const int hi = kr < 4 ? kr : 6 - kr;
            const float2 fa = __half22float2(slog[lb1 + hi * 2]);
            const float2 fb = __half22float2(slog[lb1 + hi * 2 + 1]);
            wl1[0] = fa.x; wl1[1] = fa.y; wl1[2] = fb.x; wl1[3] = fb.y;
        }

#pragma unroll
        for (int j = 0; j < 7; ++j) {
            const int hj = j < 4 ? j : 6 - j;
            // One shared read per (i,j) cell, consumed by both pixels.
            const float4 v = sgx[row][tx + j];
            const float2 u = sx2[row][tx + j];
            if (i <= 6) {
                const float s = fabsf(v.x - cc0.x) + fabsf(v.y - cc0.y) +
                                fabsf(v.z - cc0.z);
                const float e = ex2f(fmaf(s, -s, wl0[hj]));
                n0[0] = fmaf(v.w, e, n0[0]);
                n1[0] = fmaf(u.x, e, n1[0]);
                n2[0] = fmaf(u.y, e, n2[0]);
                dn[0] += e;
            }
            if (i >= 1) {
                const float s = fabsf(v.x - cc1.x) + fabsf(v.y - cc1.y) +
                                fabsf(v.z - cc1.z);
                const float e = ex2f(fmaf(s, -s, wl1[hj]));
                n0[1] = fmaf(v.w, e, n0[1]);
                n1[1] = fmaf(u.x, e, n1[1]);
                n2[1] = fmaf(u.y, e, n2[1]);
                dn[1] += e;
            }
        }
    }

    const float i0 = __fdividef(1.0f, dn[0]);
    const float i1 = __fdividef(1.0f, dn[1]);

    const size_t o = ((size_t)b * C * H + (size_t)h) * W + w;
    out[o]                         = n0[0] * i0;
    out[o + (size_t)H * W]         = n1[0] * i0;
    out[o + (size_t)2 * H * W]     = n2[0] * i0;
    out[o + W]                     = n0[1] * i1;
    out[o + W + (size_t)H * W]     = n1[1] * i1;
    out[o + W + (size_t)2 * H * W] = n2[1] * i1;
}

extern "C" void kernel_launch(void* const* d_in, const int* in_sizes, int n_in,
                              void* d_out, int out_size) {
    const float* x  = (const float*)d_in[0];
    const float* g  = (const float*)d_in[1];
    const float* w0 = (const float*)d_in[2];
    float* out = (float*)d_out;

    dim3 block(BX, BY);
    dim3 grid(W / TW, H / TH, B);
    adaptive_filter_kernel<<<grid, block>>>(x, g, w0, out);
}

// round 17
// speedup vs baseline: 1.1766x; 1.0111x over previous
#include <cuda_runtime.h>
#include <cuda_fp16.h>

// AdaptiveFilter: per-pixel learned bilateral filter.
// PY=2 vertical blocking, tile 32x8, 128-thread CTAs, 7 CTAs/SM (28 warps)
// at NATURAL register count (no launch-bounds squeeze). Logits staged in
// shared memory as fp16 (prescaled by log2 e, 9-half2/pixel stride ->
// conflict-free LDS.32). No pad columns (BX=32: a warp reads one smem row).
// Grid 2048 CTAs -> 1.98 waves at 7 CTAs/SM (near-perfect balance).
// out_c(p) = sum_k x_c(p+dk) * e_k / sum_k e_k,
//   e_k = 2^( w_k*log2e - (S*d_k)^2 ),  S = sqrt(50*log2e),
//   d_k = sum_c |g_c(p+dk)-g_c(p)|  (guidance pre-scaled by S in smem).
// Softmax normalizer cancels in the ratio.

namespace {
constexpr int B = 2, C = 3, H = 512, W = 512;
constexpr int BX = 32, BY = 4;       // 128 threads; warp = one 32-col row
constexpr int NT = BX * BY;
constexpr int PY = 2;                // pixels per thread (vertical)
constexpr int TW = BX;               // 32
constexpr int TH = BY * PY;          // 8
constexpr int HALO = 3;
constexpr int SW = TW + 2 * HALO;    // 38
constexpr int SH = TH + 2 * HALO;    // 14
constexpr int NPIX = TW * TH;        // 256 pixels per tile
constexpr int LS = 9;                // logit stride per pixel in half2 units
constexpr float LOG2E = 1.4426950408889634f;
constexpr float GS = 8.49321796f;    // sqrt(50*log2e)
}

__device__ __forceinline__ float ex2f(float v) {
    float r;
    asm("ex2.approx.f32 %0, %1;" : "=f"(r) : "f"(v));
    return r;
}

__global__ __launch_bounds__(NT, 7)
void adaptive_filter_kernel(const float* __restrict__ x,
                            const float* __restrict__ g,
                            const float* __restrict__ w0,
                            float* __restrict__ out) {
    // Packed shared tiles: sgx = (S*g0, S*g1, S*g2, x0), sx2 = (x1, x2).
    __shared__ float4 sgx[SH][SW];
    __shared__ float2 sx2[SH][SW];
    // Staged logits: 16 halves (8 half2) per pixel at stride 9 half2.
    __shared__ __half2 slog[NPIX * LS + 8];

    const int b   = blockIdx.z;
    const int h0  = blockIdx.y * TH;
    const int w0c = blockIdx.x * TW;
    const int tid = threadIdx.y * BX + threadIdx.x;

    const float* __restrict__ gb = g + (size_t)b * C * H * W;
    const float* __restrict__ xb = x + (size_t)b * C * H * W;

    // ---- Stage logits: 256 px * 4 float4 = 1024 float4 (128 per tile row),
    // dense cooperative LDG.128, prescale by log2e, pack fp16, scatter.
    {
        const float4* __restrict__ wsrc = reinterpret_cast<const float4*>(w0);
#pragma unroll
        for (int k = 0; k < 8; ++k) {
            const int c = tid + NT * k;    // chunk 0..1023
            const int r = c >> 7;          // tile pixel row (0..7)
            const int f = c & 127;         // float4 within this row's 128
            const float4 t = __ldg(
                &wsrc[((size_t)b * H * W + (size_t)(h0 + r) * W + w0c) * 4 + f]);
            const int id = r * 32 + (f >> 2);  // tile-local pixel id
            const int q  = f & 3;              // float4 slot within pixel
            slog[id * LS + q * 2]     = __floats2half2_rn(t.x * LOG2E, t.y * LOG2E);
            slog[id * LS + q * 2 + 1] = __floats2half2_rn(t.z * LOG2E, t.w * LOG2E);
        }
    }

    // ---- Halo load with reflect padding (pad=3 << 512, one reflection).
    for (int idx = tid; idx < SH * SW; idx += NT) {
        const int ty = idx / SW;
        const int tx = idx - ty * SW;
        int gy = h0 + ty - HALO;
        gy = gy < 0 ? -gy : (gy >= H ? 2 * H - 2 - gy : gy);
        int gx = w0c + tx - HALO;
        gx = gx < 0 ? -gx : (gx >= W ? 2 * W - 2 - gx : gx);
        const int p = gy * W + gx;
        sgx[ty][tx] = make_float4(gb[p] * GS, gb[H * W + p] * GS,
                                  gb[2 * H * W + p] * GS, xb[p]);
        sx2[ty][tx] = make_float2(xb[H * W + p], xb[2 * H * W + p]);
    }
    __syncthreads();

    const int tx  = threadIdx.x;            // 0..31 (column within tile)
    const int py0 = threadIdx.y * PY;       // tile-local row of pixel 0
    const int h   = h0 + py0;
    const int w   = w0c + tx;

    // Per-pixel logit bases (half2 index into slog).
    const int lb0 = (py0 * 32 + tx) * LS;
    const int lb1 = ((py0 + 1) * 32 + tx) * LS;

    // Center guidance (pre-scaled) per pixel.
    const float4 cc0 = sgx[py0 + HALO][tx + HALO];
    const float4 cc1 = sgx[py0 + 1 + HALO][tx + HALO];

    float n0[PY] = {0.f, 0.f}, n1[PY] = {0.f, 0.f},
          n2[PY] = {0.f, 0.f}, dn[PY] = {0.f, 0.f};

#pragma unroll
    for (int i = 0; i < 8; ++i) {            // window rows py0+i
        const int row = py0 + i;

        // Kernel-row logits from fp16 smem; compile-time predication.
        float wl0[4], wl1[4];
        if (i <= 6) {                        // pixel 0: kernel row i
            const int hi = i < 4 ? i : 6 - i;
            const float2 fa = __half22float2(slog[lb0 + hi * 2]);
            const float2 fb = __half22float2(slog[lb0 + hi * 2 + 1]);
            wl0[0] = fa.x; wl0[1] = fa.y; wl0[2] = fb.x; wl0[3] = fb.y;
        }
        if (i >= 1) {                        // pixel 1: kernel row i-1
            const int kr = i - 1;
            const int hi = kr < 4 ? kr : 6 - kr;
            const float2 fa = __half22float2(slog[lb1 + hi * 2]);
            const float2 fb = __half22float2(slog[lb1 + hi * 2 + 1]);
            wl1[0] = fa.x; wl1[1] = fa.y; wl1[2] = fb.x; wl1[3] = fb.y;
        }

#pragma unroll
        for (int j = 0; j < 7; ++j) {
            const int hj = j < 4 ? j : 6 - j;
            // One shared read per (i,j) cell, consumed by both pixels.
            const float4 v = sgx[row][tx + j];
            const float2 u = sx2[row][tx + j];
            if (i <= 6) {
                const float s = fabsf(v.x - cc0.x) + fabsf(v.y - cc0.y) +
                                fabsf(v.z - cc0.z);
                const float e = ex2f(fmaf(s, -s, wl0[hj]));
                n0[0] = fmaf(v.w, e, n0[0]);
                n1[0] = fmaf(u.x, e, n1[0]);
                n2[0] = fmaf(u.y, e, n2[0]);
                dn[0] += e;
            }
            if (i >= 1) {
                const float s = fabsf(v.x - cc1.x) + fabsf(v.y - cc1.y) +
                                fabsf(v.z - cc1.z);
                const float e = ex2f(fmaf(s, -s, wl1[hj]));
                n0[1] = fmaf(v.w, e, n0[1]);
                n1[1] = fmaf(u.x, e, n1[1]);
                n2[1] = fmaf(u.y, e, n2[1]);
                dn[1] += e;
            }
        }
    }

    const float i0 = __fdividef(1.0f, dn[0]);
    const float i1 = __fdividef(1.0f, dn[1]);

    const size_t o = ((size_t)b * C * H + (size_t)h) * W + w;
    out[o]                         = n0[0] * i0;
    out[o + (size_t)H * W]         = n1[0] * i0;
    out[o + (size_t)2 * H * W]     = n2[0] * i0;
    out[o + W]                     = n0[1] * i1;
    out[o + W + (size_t)H * W]     = n1[1] * i1;
    out[o + W + (size_t)2 * H * W] = n2[1] * i1;
}

extern "C" void kernel_launch(void* const* d_in, const int* in_sizes, int n_in,
                              void* d_out, int out_size) {
    const float* x  = (const float*)d_in[0];
    const float* g  = (const float*)d_in[1];
    const float* w0 = (const float*)d_in[2];
    float* out = (float*)d_out;

    dim3 block(BX, BY);
    dim3 grid(W / TW, H / TH, B);
    adaptive_filter_kernel<<<grid, block>>>(x, g, w0, out);
}